// round 2
// baseline (speedup 1.0000x reference)
#include <cuda_runtime.h>
#include <math.h>

// Problem constants
#define Bn 2
#define Sn 1024
#define Dn 1024
#define NHn 16
#define HDn 64
#define En 8
#define HIDn 4096
#define Tn (Bn*Sn)          // 2048 tokens
#define MAXROWS 5248        // >= 4096 assignments + 8*127 padding, mult of 128

// ---------------- scratch (static device globals; no allocation) -------------
static __device__ float g_XN  [Tn*Dn];
static __device__ float g_Qb  [Tn*Dn];
static __device__ float g_Kb  [Tn*Dn];
static __device__ float g_Vb  [Tn*Dn];
static __device__ float g_ATT [Tn*Dn];
static __device__ float g_Hb  [Tn*Dn];
static __device__ float g_XN2 [Tn*Dn];
static __device__ float g_GBUF[MAXROWS*HIDn];
static __device__ float g_UBUF[MAXROWS*HIDn];
static __device__ int   g_cnt[En];
static __device__ int   g_cursor[En];
static __device__ int   g_rowtok[MAXROWS];
static __device__ int   g_rowexp[MAXROWS];
static __device__ float g_rowgate[MAXROWS];
static __device__ int   g_totalrows;
static __device__ float g_gsum[En];
static __device__ float g_psum[En];
static __device__ int   g_expid[Tn*2];
static __device__ float g_gateval[Tn*2];

// ---------------------------------------------------------------------------
__global__ void k_reset() {
    int i = threadIdx.x;
    if (i < En) { g_cnt[i] = 0; g_gsum[i] = 0.f; g_psum[i] = 0.f; }
}

// RMSNorm: one block per token, 256 threads * 4 floats = 1024
__global__ void k_rmsnorm(const float* __restrict__ x, const float* __restrict__ w,
                          float* __restrict__ y) {
    int t = blockIdx.x;
    const float* xr = x + (size_t)t * Dn;
    int base = threadIdx.x * 4;
    float4 xv = *(const float4*)(xr + base);
    float ss = xv.x*xv.x + xv.y*xv.y + xv.z*xv.z + xv.w*xv.w;
    #pragma unroll
    for (int o = 16; o; o >>= 1) ss += __shfl_xor_sync(0xffffffffu, ss, o);
    __shared__ float ws[8];
    if ((threadIdx.x & 31) == 0) ws[threadIdx.x >> 5] = ss;
    __syncthreads();
    float tot = ws[0]+ws[1]+ws[2]+ws[3]+ws[4]+ws[5]+ws[6]+ws[7];
    float sc = rsqrtf(tot * (1.f/(float)Dn) + 1e-6f);
    float4 wv = *(const float4*)(w + base);
    float4 o4;
    o4.x = wv.x*xv.x*sc; o4.y = wv.y*xv.y*sc;
    o4.z = wv.z*xv.z*sc; o4.w = wv.w*xv.w*sc;
    *(float4*)(y + (size_t)t*Dn + base) = o4;
}

// Generic C = A(MxK) * B(NxK)^T, 128x128x8 tiles, 8x8 per thread.
// Optional residual add and dual-output.
__global__ __launch_bounds__(256)
void k_sgemm_nt(const float* __restrict__ A, int lda,
                const float* __restrict__ Bw, int ldb,
                float* __restrict__ C, int ldc, int K,
                const float* __restrict__ resid, float* __restrict__ C2)
{
    __shared__ float As[8][128];
    __shared__ float Bs[8][128];
    int tid = threadIdx.x;
    int arow = blockIdx.y*128 + (tid>>1);
    int brow = blockIdx.x*128 + (tid>>1);
    int ak = (tid&1)*4;
    const float* Ap = A + (size_t)arow*lda + ak;
    const float* Bp = Bw + (size_t)brow*ldb + ak;
    int r0 = (tid>>4)*8, c0 = (tid&15)*8;
    float acc[8][8];
    #pragma unroll
    for (int i=0;i<8;i++)
        #pragma unroll
        for (int j=0;j<8;j++) acc[i][j]=0.f;
    for (int k0=0;k0<K;k0+=8){
        float4 av = *(const float4*)(Ap + k0);
        float4 bv = *(const float4*)(Bp + k0);
        As[ak+0][tid>>1]=av.x; As[ak+1][tid>>1]=av.y;
        As[ak+2][tid>>1]=av.z; As[ak+3][tid>>1]=av.w;
        Bs[ak+0][tid>>1]=bv.x; Bs[ak+1][tid>>1]=bv.y;
        Bs[ak+2][tid>>1]=bv.z; Bs[ak+3][tid>>1]=bv.w;
        __syncthreads();
        #pragma unroll
        for (int kk=0; kk<8; kk++){
            float a[8], b[8];
            *(float4*)(a)   = *(const float4*)&As[kk][r0];
            *(float4*)(a+4) = *(const float4*)&As[kk][r0+4];
            *(float4*)(b)   = *(const float4*)&Bs[kk][c0];
            *(float4*)(b+4) = *(const float4*)&Bs[kk][c0+4];
            #pragma unroll
            for (int i=0;i<8;i++)
                #pragma unroll
                for (int j=0;j<8;j++) acc[i][j] = fmaf(a[i], b[j], acc[i][j]);
        }
        __syncthreads();
    }
    int mbase = blockIdx.y*128 + r0;
    int nbase = blockIdx.x*128 + c0;
    #pragma unroll
    for (int i=0;i<8;i++){
        size_t ro = (size_t)(mbase+i)*ldc;
        #pragma unroll
        for (int j=0;j<8;j++){
            float v = acc[i][j];
            if (resid) v += resid[ro + nbase + j];
            C[ro + nbase + j] = v;
            if (C2) C2[ro + nbase + j] = v;
        }
    }
}

// MoE input GEMM: rows gathered via g_rowtok, weight chosen per 128-row tile's expert.
__global__ __launch_bounds__(256)
void k_sgemm_moe_in(const float* __restrict__ Xn, const float* __restrict__ Wall,
                    float* __restrict__ C)
{
    if ((int)(blockIdx.y*128) >= g_totalrows) return;
    __shared__ float As[8][128];
    __shared__ float Bs[8][128];
    int e = g_rowexp[blockIdx.y*128];
    const float* Bw = Wall + (size_t)e * HIDn * Dn;
    int tid = threadIdx.x;
    int m = blockIdx.y*128 + (tid>>1);
    int tok = g_rowtok[m];
    int ak = (tid&1)*4;
    const float* Ap = (tok >= 0) ? (Xn + (size_t)tok*Dn + ak) : (const float*)0;
    const float* Bp = Bw + (size_t)(blockIdx.x*128 + (tid>>1))*Dn + ak;
    int r0 = (tid>>4)*8, c0 = (tid&15)*8;
    float acc[8][8];
    #pragma unroll
    for (int i=0;i<8;i++)
        #pragma unroll
        for (int j=0;j<8;j++) acc[i][j]=0.f;
    for (int k0=0;k0<Dn;k0+=8){
        float4 av = Ap ? *(const float4*)(Ap + k0) : make_float4(0.f,0.f,0.f,0.f);
        float4 bv = *(const float4*)(Bp + k0);
        As[ak+0][tid>>1]=av.x; As[ak+1][tid>>1]=av.y;
        As[ak+2][tid>>1]=av.z; As[ak+3][tid>>1]=av.w;
        Bs[ak+0][tid>>1]=bv.x; Bs[ak+1][tid>>1]=bv.y;
        Bs[ak+2][tid>>1]=bv.z; Bs[ak+3][tid>>1]=bv.w;
        __syncthreads();
        #pragma unroll
        for (int kk=0; kk<8; kk++){
            float a[8], b[8];
            *(float4*)(a)   = *(const float4*)&As[kk][r0];
            *(float4*)(a+4) = *(const float4*)&As[kk][r0+4];
            *(float4*)(b)   = *(const float4*)&Bs[kk][c0];
            *(float4*)(b+4) = *(const float4*)&Bs[kk][c0+4];
            #pragma unroll
            for (int i=0;i<8;i++)
                #pragma unroll
                for (int j=0;j<8;j++) acc[i][j] = fmaf(a[i], b[j], acc[i][j]);
        }
        __syncthreads();
    }
    int mbase = blockIdx.y*128 + r0;
    int nbase = blockIdx.x*128 + c0;
    #pragma unroll
    for (int i=0;i<8;i++){
        size_t ro = (size_t)(mbase+i)*HIDn;
        #pragma unroll
        for (int j=0;j<8;j++) C[ro + nbase + j] = acc[i][j];
    }
}

// Down GEMM: C=(H @ Wd^T); epilogue scatters gate*val into out via atomicAdd.
__global__ __launch_bounds__(256)
void k_sgemm_moe_down(const float* __restrict__ Hbuf, const float* __restrict__ Wall,
                      float* __restrict__ out)
{
    if ((int)(blockIdx.y*128) >= g_totalrows) return;
    __shared__ float As[8][128];
    __shared__ float Bs[8][128];
    int e = g_rowexp[blockIdx.y*128];
    const float* Bw = Wall + (size_t)e * Dn * HIDn;
    int tid = threadIdx.x;
    int m = blockIdx.y*128 + (tid>>1);
    int ak = (tid&1)*4;
    const float* Ap = Hbuf + (size_t)m*HIDn + ak;
    const float* Bp = Bw + (size_t)(blockIdx.x*128 + (tid>>1))*HIDn + ak;
    int r0 = (tid>>4)*8, c0 = (tid&15)*8;
    float acc[8][8];
    #pragma unroll
    for (int i=0;i<8;i++)
        #pragma unroll
        for (int j=0;j<8;j++) acc[i][j]=0.f;
    for (int k0=0;k0<HIDn;k0+=8){
        float4 av = *(const float4*)(Ap + k0);
        float4 bv = *(const float4*)(Bp + k0);
        As[ak+0][tid>>1]=av.x; As[ak+1][tid>>1]=av.y;
        As[ak+2][tid>>1]=av.z; As[ak+3][tid>>1]=av.w;
        Bs[ak+0][tid>>1]=bv.x; Bs[ak+1][tid>>1]=bv.y;
        Bs[ak+2][tid>>1]=bv.z; Bs[ak+3][tid>>1]=bv.w;
        __syncthreads();
        #pragma unroll
        for (int kk=0; kk<8; kk++){
            float a[8], b[8];
            *(float4*)(a)   = *(const float4*)&As[kk][r0];
            *(float4*)(a+4) = *(const float4*)&As[kk][r0+4];
            *(float4*)(b)   = *(const float4*)&Bs[kk][c0];
            *(float4*)(b+4) = *(const float4*)&Bs[kk][c0+4];
            #pragma unroll
            for (int i=0;i<8;i++)
                #pragma unroll
                for (int j=0;j<8;j++) acc[i][j] = fmaf(a[i], b[j], acc[i][j]);
        }
        __syncthreads();
    }
    int mbase = blockIdx.y*128 + r0;
    int nbase = blockIdx.x*128 + c0;
    #pragma unroll
    for (int i=0;i<8;i++){
        int row = mbase + i;
        int tok = g_rowtok[row];
        if (tok >= 0){
            float gv = g_rowgate[row];
            #pragma unroll
            for (int j=0;j<8;j++)
                atomicAdd(&out[(size_t)tok*Dn + nbase + j], gv*acc[i][j]);
        }
    }
}

// RoPE in-place: one thread per (token, head, pair-index)
__global__ void k_rope(float* __restrict__ q) {
    int idx = blockIdx.x*blockDim.x + threadIdx.x;
    if (idx >= Tn*NHn*32) return;
    int i = idx & 31;
    int h = (idx >> 5) & (NHn-1);
    int t = idx >> 9;
    int s = t & (Sn-1);
    float invf = powf(10000.f, -((float)(2*i)) * (1.f/(float)HDn));
    float fr = (float)s * invf;
    float c, sn;
    sincosf(fr, &sn, &c);
    float* p = q + (size_t)t*Dn + h*HDn + i;
    float v1 = p[0], v2 = p[32];
    p[0]  = v1*c - v2*sn;
    p[32] = v2*c + v1*sn;
}

// Flash attention: block = (b,h, qtile of 64), 256 threads, online softmax
__global__ __launch_bounds__(256)
void k_attn(const float* __restrict__ Q, const float* __restrict__ Kg,
            const float* __restrict__ V, float* __restrict__ O)
{
    __shared__ float Qs [64*64];
    __shared__ float KVs[64*64];
    __shared__ float Ps [64*64];
    int bh = blockIdx.x;
    int qt = blockIdx.y;
    int b = bh >> 4, h = bh & 15;
    int tid = threadIdx.x;
    int ty = tid >> 4, tx = tid & 15;
    size_t base = ((size_t)b*Sn)*Dn + (size_t)h*HDn;
    int q0 = qt*64;
    #pragma unroll
    for (int rep=0;rep<4;rep++){
        int lin = tid + rep*256;
        int r = lin >> 4, c = (lin & 15)*4;
        *(float4*)&Qs[r*64+c] = *(const float4*)(Q + base + (size_t)(q0+r)*Dn + c);
    }
    float acc[4][4];
    float mrow[4], lrow[4];
    #pragma unroll
    for (int i=0;i<4;i++){
        mrow[i] = -1e30f; lrow[i] = 0.f;
        #pragma unroll
        for (int j=0;j<4;j++) acc[i][j]=0.f;
    }
    __syncthreads();
    for (int kt=0; kt<=qt; kt++){
        int k0 = kt*64;
        // K tile, transposed to [hd][key]
        #pragma unroll
        for (int rep=0;rep<4;rep++){
            int lin = tid + rep*256;
            int r = lin >> 4, c = (lin & 15)*4;
            float4 kv = *(const float4*)(Kg + base + (size_t)(k0+r)*Dn + c);
            KVs[(c+0)*64 + r] = kv.x;
            KVs[(c+1)*64 + r] = kv.y;
            KVs[(c+2)*64 + r] = kv.z;
            KVs[(c+3)*64 + r] = kv.w;
        }
        __syncthreads();
        float s[4][4];
        #pragma unroll
        for (int i=0;i<4;i++)
            #pragma unroll
            for (int j=0;j<4;j++) s[i][j]=0.f;
        #pragma unroll 4
        for (int d=0; d<64; d++){
            float qa[4], kb[4];
            #pragma unroll
            for (int i=0;i<4;i++) qa[i] = Qs[(ty*4+i)*64 + d];
            #pragma unroll
            for (int j=0;j<4;j++) kb[j] = KVs[d*64 + tx*4 + j];
            #pragma unroll
            for (int i=0;i<4;i++)
                #pragma unroll
                for (int j=0;j<4;j++) s[i][j] = fmaf(qa[i], kb[j], s[i][j]);
        }
        #pragma unroll
        for (int i=0;i<4;i++){
            int qq = q0 + ty*4 + i;
            #pragma unroll
            for (int j=0;j<4;j++){
                int kk = k0 + tx*4 + j;
                s[i][j] = (kk <= qq) ? s[i][j]*0.125f : -1e30f;
            }
        }
        #pragma unroll
        for (int i=0;i<4;i++){
            float mt = fmaxf(fmaxf(s[i][0],s[i][1]), fmaxf(s[i][2],s[i][3]));
            #pragma unroll
            for (int o=8;o;o>>=1) mt = fmaxf(mt, __shfl_xor_sync(0xffffffffu, mt, o));
            float mn = fmaxf(mrow[i], mt);
            float corr = __expf(mrow[i] - mn);
            float rs = 0.f;
            #pragma unroll
            for (int j=0;j<4;j++){ float p = __expf(s[i][j]-mn); s[i][j]=p; rs+=p; }
            #pragma unroll
            for (int o=8;o;o>>=1) rs += __shfl_xor_sync(0xffffffffu, rs, o);
            lrow[i] = lrow[i]*corr + rs;
            mrow[i] = mn;
            #pragma unroll
            for (int j=0;j<4;j++) acc[i][j] *= corr;
            #pragma unroll
            for (int j=0;j<4;j++) Ps[(ty*4+i)*64 + tx*4+j] = s[i][j];
        }
        __syncthreads();
        // V tile (natural [key][hd]) reuses KVs
        #pragma unroll
        for (int rep=0;rep<4;rep++){
            int lin = tid + rep*256;
            int r = lin >> 4, c = (lin & 15)*4;
            *(float4*)&KVs[r*64+c] = *(const float4*)(V + base + (size_t)(k0+r)*Dn + c);
        }
        __syncthreads();
        #pragma unroll 4
        for (int kv=0; kv<64; kv++){
            float pv[4], vv[4];
            #pragma unroll
            for (int i=0;i<4;i++) pv[i] = Ps[(ty*4+i)*64 + kv];
            #pragma unroll
            for (int j=0;j<4;j++) vv[j] = KVs[kv*64 + tx*4 + j];
            #pragma unroll
            for (int i=0;i<4;i++)
                #pragma unroll
                for (int j=0;j<4;j++) acc[i][j] = fmaf(pv[i], vv[j], acc[i][j]);
        }
        __syncthreads();
    }
    #pragma unroll
    for (int i=0;i<4;i++){
        float inv = 1.f/lrow[i];
        #pragma unroll
        for (int j=0;j<4;j++)
            O[base + (size_t)(q0+ty*4+i)*Dn + tx*4 + j] = acc[i][j]*inv;
    }
}

// Gate: one block per token; warp e computes logit e; thread0 does top-2 + aux sums
__global__ void k_gate(const float* __restrict__ xn, const float* __restrict__ gw)
{
    int t = blockIdx.x;
    int w = threadIdx.x >> 5, lane = threadIdx.x & 31;
    const float* xr = xn + (size_t)t * Dn;
    const float* gr = gw + (size_t)w * Dn;
    float acc = 0.f;
    for (int d = lane; d < Dn; d += 32) acc = fmaf(xr[d], gr[d], acc);
    #pragma unroll
    for (int o=16;o;o>>=1) acc += __shfl_xor_sync(0xffffffffu, acc, o);
    __shared__ float lg[En];
    if (lane == 0) lg[w] = acc;
    __syncthreads();
    if (threadIdx.x == 0){
        int i1 = 0;
        for (int e=1;e<En;e++) if (lg[e] > lg[i1]) i1 = e;
        int i2 = -1;
        for (int e=0;e<En;e++){
            if (e == i1) continue;
            if (i2 < 0 || lg[e] > lg[i2]) i2 = e;
        }
        float l1 = lg[i1], l2 = lg[i2];
        float e2 = expf(l2 - l1);
        float inv = 1.f/(1.f + e2);
        float gv1 = inv, gv2 = e2*inv;
        g_expid[t*2]   = i1; g_expid[t*2+1]   = i2;
        g_gateval[t*2] = gv1; g_gateval[t*2+1] = gv2;
        atomicAdd(&g_cnt[i1], 1); atomicAdd(&g_cnt[i2], 1);
        atomicAdd(&g_gsum[i1], gv1); atomicAdd(&g_gsum[i2], gv2);
        float mx = lg[0];
        for (int e=1;e<En;e++) mx = fmaxf(mx, lg[e]);
        float pe[En]; float se = 0.f;
        for (int e=0;e<En;e++){ pe[e] = expf(lg[e]-mx); se += pe[e]; }
        float pinv = 1.f/se;
        for (int e=0;e<En;e++) atomicAdd(&g_psum[e], pe[e]*pinv);
    }
}

// Offsets (128-aligned per expert), region expert map, aux loss
__global__ void k_offsets(float* __restrict__ out, int write_aux)
{
    __shared__ int soff[En+1];
    if (threadIdx.x == 0){
        int tot = 0;
        for (int e=0;e<En;e++){
            soff[e] = tot;
            g_cursor[e] = tot;
            tot += ((g_cnt[e] + 127) >> 7) << 7;
        }
        soff[En] = tot;
        g_totalrows = tot;
        if (write_aux){
            float sacc = 0.f;
            for (int e=0;e<En;e++) sacc += g_gsum[e]*g_psum[e];
            out[(size_t)Tn*Dn] = (float)En * sacc / ((float)Tn*(float)Tn);
        }
    }
    __syncthreads();
    int tot = soff[En];
    for (int r = threadIdx.x; r < tot; r += blockDim.x){
        int e = 0;
        while (e+1 < En && r >= soff[e+1]) e++;
        g_rowexp[r] = e;
        g_rowtok[r] = -1;
    }
}

__global__ void k_scatter()
{
    int t = blockIdx.x*blockDim.x + threadIdx.x;
    if (t >= Tn) return;
    #pragma unroll
    for (int k=0;k<2;k++){
        int e = g_expid[t*2+k];
        int pos = atomicAdd(&g_cursor[e], 1);
        g_rowtok[pos] = t;
        g_rowgate[pos] = g_gateval[t*2+k];
    }
}

// H = silu(G) * U (in place into GBUF)
__global__ void k_silumul()
{
    size_t i4 = ((size_t)blockIdx.x*blockDim.x + threadIdx.x) * 4;
    size_t n = (size_t)g_totalrows * HIDn;
    if (i4 >= n) return;
    float4 g = *(float4*)&g_GBUF[i4];
    float4 u = *(float4*)&g_UBUF[i4];
    g.x = (g.x / (1.f + expf(-g.x))) * u.x;
    g.y = (g.y / (1.f + expf(-g.y))) * u.y;
    g.z = (g.z / (1.f + expf(-g.z))) * u.z;
    g.w = (g.w / (1.f + expf(-g.w))) * u.w;
    *(float4*)&g_GBUF[i4] = g;
}

// ---------------------------------------------------------------------------
extern "C" void kernel_launch(void* const* d_in, const int* in_sizes, int n_in,
                              void* d_out, int out_size)
{
    (void)in_sizes; (void)n_in;
    const float* x   = (const float*)d_in[0];
    const float* wq  = (const float*)d_in[1];
    const float* wk  = (const float*)d_in[2];
    const float* wv  = (const float*)d_in[3];
    const float* wo  = (const float*)d_in[4];
    const float* anw = (const float*)d_in[5];
    const float* fnw = (const float*)d_in[6];
    const float* gw  = (const float*)d_in[7];
    const float* wge = (const float*)d_in[8];
    const float* wue = (const float*)d_in[9];
    const float* wde = (const float*)d_in[10];
    float* out = (float*)d_out;

    float *pXN,*pQ,*pK,*pV,*pATT,*pH,*pXN2,*pG,*pU;
    cudaGetSymbolAddress((void**)&pXN,  g_XN);
    cudaGetSymbolAddress((void**)&pQ,   g_Qb);
    cudaGetSymbolAddress((void**)&pK,   g_Kb);
    cudaGetSymbolAddress((void**)&pV,   g_Vb);
    cudaGetSymbolAddress((void**)&pATT, g_ATT);
    cudaGetSymbolAddress((void**)&pH,   g_Hb);
    cudaGetSymbolAddress((void**)&pXN2, g_XN2);
    cudaGetSymbolAddress((void**)&pG,   g_GBUF);
    cudaGetSymbolAddress((void**)&pU,   g_UBUF);

    k_reset<<<1, 32>>>();

    // attn pre-norm
    k_rmsnorm<<<Tn, 256>>>(x, anw, pXN);

    // QKV projections
    dim3 gqkv(Dn/128, Tn/128);
    k_sgemm_nt<<<gqkv, 256>>>(pXN, Dn, wq, Dn, pQ, Dn, Dn, 0, 0);
    k_sgemm_nt<<<gqkv, 256>>>(pXN, Dn, wk, Dn, pK, Dn, Dn, 0, 0);
    k_sgemm_nt<<<gqkv, 256>>>(pXN, Dn, wv, Dn, pV, Dn, Dn, 0, 0);

    // RoPE
    int nrope = Tn*NHn*32;
    k_rope<<<nrope/256, 256>>>(pQ);
    k_rope<<<nrope/256, 256>>>(pK);

    // attention
    k_attn<<<dim3(Bn*NHn, Sn/64), 256>>>(pQ, pK, pV, pATT);

    // out proj + residual (writes H and d_out)
    k_sgemm_nt<<<gqkv, 256>>>(pATT, Dn, wo, Dn, pH, Dn, Dn, x, out);

    // ffn pre-norm
    k_rmsnorm<<<Tn, 256>>>(pH, fnw, pXN2);

    // gating + routing
    k_gate<<<Tn, 256>>>(pXN2, gw);
    int write_aux = (out_size > Tn*Dn) ? 1 : 0;
    k_offsets<<<1, 256>>>(out, write_aux);
    k_scatter<<<(Tn+255)/256, 256>>>();

    // expert gate/up GEMMs (gathered rows, per-tile expert weights)
    dim3 gin(HIDn/128, MAXROWS/128);
    k_sgemm_moe_in<<<gin, 256>>>(pXN2, wge, pG);
    k_sgemm_moe_in<<<gin, 256>>>(pXN2, wue, pU);

    // SwiGLU elementwise
    k_silumul<<<(MAXROWS*(HIDn/4))/256, 256>>>();

    // down GEMM + gated scatter-add into out
    dim3 gdn(Dn/128, MAXROWS/128);
    k_sgemm_moe_down<<<gdn, 256>>>(pG, wde, out);
}

// round 4
// speedup vs baseline: 4.8336x; 4.8336x over previous
#include <cuda_runtime.h>
#include <cuda_fp16.h>
#include <math.h>
#include <stdint.h>

// Problem constants
#define Bn 2
#define Sn 1024
#define Dn 1024
#define NHn 16
#define HDn 64
#define En 8
#define HIDn 4096
#define Tn (Bn*Sn)          // 2048 tokens
#define MAXROWS 5248        // >= 4096 assignments + 8*127 padding, mult of 128

// ---------------- scratch (static device globals; no allocation) -------------
static __device__ __half g_XNh [Tn*Dn];
static __device__ float  g_Qb  [Tn*Dn];
static __device__ float  g_Kb  [Tn*Dn];
static __device__ float  g_Vb  [Tn*Dn];
static __device__ __half g_ATTh[Tn*Dn];
static __device__ float  g_Hb  [Tn*Dn];
static __device__ float  g_XN2 [Tn*Dn];
static __device__ __half g_XN2h[Tn*Dn];
static __device__ float  g_GBUF[(size_t)MAXROWS*HIDn];
static __device__ float  g_UBUF[(size_t)MAXROWS*HIDn];
static __device__ __half g_Hh  [(size_t)MAXROWS*HIDn];
// fp16 weights
static __device__ __half g_Wqh[Dn*Dn];
static __device__ __half g_Wkh[Dn*Dn];
static __device__ __half g_Wvh[Dn*Dn];
static __device__ __half g_Woh[Dn*Dn];
static __device__ __half g_Wgeh[(size_t)En*HIDn*Dn];
static __device__ __half g_Wueh[(size_t)En*HIDn*Dn];
static __device__ __half g_Wdeh[(size_t)En*Dn*HIDn];
// routing
static __device__ int   g_cnt[En];
static __device__ int   g_cursor[En];
static __device__ int   g_rowtok[MAXROWS];
static __device__ int   g_rowexp[MAXROWS];
static __device__ float g_rowgate[MAXROWS];
static __device__ int   g_totalrows;
static __device__ float g_gsum[En];
static __device__ float g_psum[En];
static __device__ int   g_expid[Tn*2];
static __device__ float g_gateval[Tn*2];

// ======================= PTX helpers =========================================
static __device__ __forceinline__ uint32_t smem_u32_(const void* p){
    uint32_t a;
    asm("{ .reg .u64 t; cvta.to.shared.u64 t, %1; cvt.u32.u64 %0, t; }"
        : "=r"(a) : "l"(p));
    return a;
}

#define LDSM_X4(r0,r1,r2,r3,addr) \
    asm volatile("ldmatrix.sync.aligned.m8n8.x4.shared.b16 {%0,%1,%2,%3}, [%4];" \
        : "=r"(r0),"=r"(r1),"=r"(r2),"=r"(r3) : "r"(addr))

#define MMA16816(c,a,b) \
    asm volatile("mma.sync.aligned.m16n8k16.row.col.f32.f16.f16.f32 " \
        "{%0,%1,%2,%3}, {%4,%5,%6,%7}, {%8,%9}, {%0,%1,%2,%3};" \
        : "+f"((c)[0]),"+f"((c)[1]),"+f"((c)[2]),"+f"((c)[3]) \
        : "r"((a)[0]),"r"((a)[1]),"r"((a)[2]),"r"((a)[3]), \
          "r"((b)[0]),"r"((b)[1]))

#define CP_COMMIT() asm volatile("cp.async.commit_group;" ::: "memory")
#define CP_WAIT(N)  asm volatile("cp.async.wait_group %0;" :: "n"(N) : "memory")

static __device__ __forceinline__ void cp16_(uint32_t dst, const void* src, int srcsize){
    asm volatile("cp.async.cg.shared.global [%0], [%1], 16, %2;"
        :: "r"(dst), "l"((unsigned long long)__cvta_generic_to_global(src)),
           "r"(srcsize) : "memory");
}

// ============================== small kernels ================================
__global__ void k_reset() {
    int i = threadIdx.x;
    if (i < En) { g_cnt[i] = 0; g_gsum[i] = 0.f; g_psum[i] = 0.f; }
}

__global__ void k_f2h(const float4* __restrict__ s, uint2* __restrict__ d, int n4){
    int i = blockIdx.x*blockDim.x + threadIdx.x;
    if (i >= n4) return;
    float4 v = s[i];
    __half2 h0 = __floats2half2_rn(v.x, v.y);
    __half2 h1 = __floats2half2_rn(v.z, v.w);
    uint2 o;
    o.x = *reinterpret_cast<uint32_t*>(&h0);
    o.y = *reinterpret_cast<uint32_t*>(&h1);
    d[i] = o;
}

__global__ void k_rmsnorm(const float* __restrict__ x, const float* __restrict__ w,
                          float* __restrict__ y, __half* __restrict__ yh) {
    int t = blockIdx.x;
    const float* xr = x + (size_t)t * Dn;
    int base = threadIdx.x * 4;
    float4 xv = *(const float4*)(xr + base);
    float ss = xv.x*xv.x + xv.y*xv.y + xv.z*xv.z + xv.w*xv.w;
    #pragma unroll
    for (int o = 16; o; o >>= 1) ss += __shfl_xor_sync(0xffffffffu, ss, o);
    __shared__ float ws[8];
    if ((threadIdx.x & 31) == 0) ws[threadIdx.x >> 5] = ss;
    __syncthreads();
    float tot = ws[0]+ws[1]+ws[2]+ws[3]+ws[4]+ws[5]+ws[6]+ws[7];
    float sc = rsqrtf(tot * (1.f/(float)Dn) + 1e-6f);
    float4 wv = *(const float4*)(w + base);
    float4 o4;
    o4.x = wv.x*xv.x*sc; o4.y = wv.y*xv.y*sc;
    o4.z = wv.z*xv.z*sc; o4.w = wv.w*xv.w*sc;
    if (y) *(float4*)(y + (size_t)t*Dn + base) = o4;
    __half2 h0 = __floats2half2_rn(o4.x, o4.y);
    __half2 h1 = __floats2half2_rn(o4.z, o4.w);
    uint2 ho;
    ho.x = *reinterpret_cast<uint32_t*>(&h0);
    ho.y = *reinterpret_cast<uint32_t*>(&h1);
    *(uint2*)(yh + (size_t)t*Dn + base) = ho;
}

// ===================== mma.sync GEMM (HMMA tensor path) ======================
// C[128*mt.., 128*nt..] = A(fp16,lda) @ B(fp16,ldb)^T, fp32 accum.
// Tile 128x128x64, 3-stage cp.async pipeline, 8 warps (4x2), m16n8k16.
#define EPI_PLAIN 0
#define EPI_RESID 1
#define EPI_DOWN  2
#define GEMM_SMEM (3*32768)

template<int NITER, int EPI, bool GATHER, bool ESEL>
__global__ __launch_bounds__(256)
void k_gemm(const __half* __restrict__ A0, int lda,
            const __half* __restrict__ B0, const __half* __restrict__ B1,
            const __half* __restrict__ B2,
            long bstride, int ldb,
            float* __restrict__ C0, float* __restrict__ C1c, float* __restrict__ C2c,
            int ldc,
            const float* __restrict__ resid, float* __restrict__ Cdual)
{
    constexpr int S = 3;
    int mt = blockIdx.y, nt = blockIdx.x;
    if (ESEL && mt*128 >= g_totalrows) return;
    const __half* Bh = (blockIdx.z==0) ? B0 : ((blockIdx.z==1) ? B1 : B2);
    float* C = (blockIdx.z==0) ? C0 : ((blockIdx.z==1) ? C1c : C2c);
    if (ESEL) Bh += (long)g_rowexp[mt*128] * bstride;

    extern __shared__ __align__(128) char sm_[];
    uint32_t sbase = smem_u32_(sm_);

    int tid = threadIdx.x, lane = tid & 31, wid = tid >> 5;
    int warp_m = wid & 3, warp_n = wid >> 2;

    // ---- staging assignment: row = tid/2, 4 chunks of 16B each half-row ----
    int lrow = tid >> 1;
    int lc0  = (tid & 1) * 4;
    const __half* asrc;
    bool avalid = true;
    if (GATHER){
        int tok = g_rowtok[mt*128 + lrow];
        avalid = (tok >= 0);
        asrc = A0 + (avalid ? (size_t)tok * lda : 0);
    } else {
        asrc = A0 + (size_t)(mt*128 + lrow) * lda;
    }
    const __half* bsrc = Bh + (size_t)(nt*128 + lrow) * ldb;
    int asz = avalid ? 16 : 0;
    uint32_t arow_s = sbase + lrow*128;
    uint32_t brow_s = arow_s + 16384;

    auto stg = [&](int it){
        int stage = it % S;
        uint32_t so = (uint32_t)stage * 32768u;
        const char* ag = (const char*)(asrc + it*64);
        const char* bg = (const char*)(bsrc + it*64);
        #pragma unroll
        for (int i = 0; i < 4; i++){
            int c = lc0 + i;
            uint32_t sw = (uint32_t)((c ^ (lrow & 7)) * 16);
            cp16_(arow_s + so + sw, ag + c*16, asz);
            cp16_(brow_s + so + sw, bg + c*16, 16);
        }
    };

    float acc[2][8][4];
    #pragma unroll
    for (int i=0;i<2;i++)
        #pragma unroll
        for (int j=0;j<8;j++)
            #pragma unroll
            for (int k=0;k<4;k++) acc[i][j][k]=0.f;

    // prologue: stages 0..S-2
    #pragma unroll
    for (int it = 0; it < S-1; it++){ stg(it); CP_COMMIT(); }

    // precomputed ldmatrix row/col pieces
    int a_rlo = (lane & 15);           // row within 16-row tile
    int a_chk = (lane >> 4);           // 0/1 -> k chunk
    int b_rlo = (lane & 7) + ((lane & 16) ? 8 : 0);
    int b_chk = (lane >> 3) & 1;

    for (int it = 0; it < NITER; it++){
        CP_WAIT(S-2);
        __syncthreads();
        if (it + S-1 < NITER) stg(it + S-1);
        CP_COMMIT();

        uint32_t so = (uint32_t)(it % S) * 32768u;
        uint32_t abase = sbase + so;
        uint32_t bbase = abase + 16384;

        #pragma unroll
        for (int ks = 0; ks < 4; ks++){
            uint32_t a[2][4];
            #pragma unroll
            for (int mtile = 0; mtile < 2; mtile++){
                int row = warp_m*32 + mtile*16 + a_rlo;
                int chunk = 2*ks + a_chk;
                uint32_t addr = abase + row*128 + ((chunk ^ (row & 7)) * 16);
                LDSM_X4(a[mtile][0], a[mtile][1], a[mtile][2], a[mtile][3], addr);
            }
            uint32_t b[8][2];
            #pragma unroll
            for (int n2 = 0; n2 < 4; n2++){
                int row = warp_n*64 + n2*16 + b_rlo;
                int chunk = 2*ks + b_chk;
                uint32_t addr = bbase + row*128 + ((chunk ^ (row & 7)) * 16);
                uint32_t r0,r1,r2,r3;
                LDSM_X4(r0, r1, r2, r3, addr);
                b[2*n2][0]=r0; b[2*n2][1]=r1;
                b[2*n2+1][0]=r2; b[2*n2+1][1]=r3;
            }
            #pragma unroll
            for (int mtile = 0; mtile < 2; mtile++)
                #pragma unroll
                for (int n8 = 0; n8 < 8; n8++)
                    MMA16816(acc[mtile][n8], a[mtile], b[n8]);
        }
        __syncthreads();
    }

    // ---- epilogue ----
    int m0 = mt*128 + warp_m*32;
    int n0 = nt*128 + warp_n*64;
    int gq = lane >> 2, tq = lane & 3;
    #pragma unroll
    for (int mtile = 0; mtile < 2; mtile++){
        int r_lo = m0 + mtile*16 + gq;
        int r_hi = r_lo + 8;
        if (EPI == EPI_DOWN){
            int tok_lo = g_rowtok[r_lo], tok_hi = g_rowtok[r_hi];
            float gl = g_rowgate[r_lo], gh = g_rowgate[r_hi];
            #pragma unroll
            for (int n8 = 0; n8 < 8; n8++){
                int col = n0 + n8*8 + tq*2;
                if (tok_lo >= 0){
                    size_t o = (size_t)tok_lo*ldc + col;
                    atomicAdd(&C[o],   gl*acc[mtile][n8][0]);
                    atomicAdd(&C[o+1], gl*acc[mtile][n8][1]);
                }
                if (tok_hi >= 0){
                    size_t o = (size_t)tok_hi*ldc + col;
                    atomicAdd(&C[o],   gh*acc[mtile][n8][2]);
                    atomicAdd(&C[o+1], gh*acc[mtile][n8][3]);
                }
            }
        } else if (EPI == EPI_RESID){
            #pragma unroll
            for (int n8 = 0; n8 < 8; n8++){
                int col = n0 + n8*8 + tq*2;
                size_t o_lo = (size_t)r_lo*ldc + col;
                size_t o_hi = (size_t)r_hi*ldc + col;
                float2 rv0 = *(const float2*)(resid + o_lo);
                float2 rv1 = *(const float2*)(resid + o_hi);
                float2 v0, v1;
                v0.x = acc[mtile][n8][0] + rv0.x;
                v0.y = acc[mtile][n8][1] + rv0.y;
                v1.x = acc[mtile][n8][2] + rv1.x;
                v1.y = acc[mtile][n8][3] + rv1.y;
                *(float2*)(C + o_lo) = v0;
                *(float2*)(C + o_hi) = v1;
                *(float2*)(Cdual + o_lo) = v0;
                *(float2*)(Cdual + o_hi) = v1;
            }
        } else {
            #pragma unroll
            for (int n8 = 0; n8 < 8; n8++){
                int col = n0 + n8*8 + tq*2;
                float2 v0, v1;
                v0.x = acc[mtile][n8][0]; v0.y = acc[mtile][n8][1];
                v1.x = acc[mtile][n8][2]; v1.y = acc[mtile][n8][3];
                *(float2*)(C + (size_t)r_lo*ldc + col) = v0;
                *(float2*)(C + (size_t)r_hi*ldc + col) = v1;
            }
        }
    }
}

// ============================ RoPE / attention ===============================
__global__ void k_rope(float* __restrict__ q) {
    int idx = blockIdx.x*blockDim.x + threadIdx.x;
    if (idx >= Tn*NHn*32) return;
    int i = idx & 31;
    int t = idx >> 9;
    int h = (idx >> 5) & (NHn-1);
    int s = t & (Sn-1);
    float invf = powf(10000.f, -((float)(2*i)) * (1.f/(float)HDn));
    float fr = (float)s * invf;
    float c, sn;
    sincosf(fr, &sn, &c);
    float* p = q + (size_t)t*Dn + h*HDn + i;
    float v1 = p[0], v2 = p[32];
    p[0]  = v1*c - v2*sn;
    p[32] = v2*c + v1*sn;
}

__global__ __launch_bounds__(256)
void k_attn(const float* __restrict__ Q, const float* __restrict__ Kg,
            const float* __restrict__ V, __half* __restrict__ O)
{
    __shared__ float Qs [64*64];
    __shared__ float KVs[64*64];
    __shared__ float Ps [64*64];
    int bh = blockIdx.x;
    int qt = blockIdx.y;
    int b = bh >> 4, h = bh & 15;
    int tid = threadIdx.x;
    int ty = tid >> 4, tx = tid & 15;
    size_t base = ((size_t)b*Sn)*Dn + (size_t)h*HDn;
    int q0 = qt*64;
    #pragma unroll
    for (int rep=0;rep<4;rep++){
        int lin = tid + rep*256;
        int r = lin >> 4, c = (lin & 15)*4;
        *(float4*)&Qs[r*64+c] = *(const float4*)(Q + base + (size_t)(q0+r)*Dn + c);
    }
    float acc[4][4];
    float mrow[4], lrow[4];
    #pragma unroll
    for (int i=0;i<4;i++){
        mrow[i] = -1e30f; lrow[i] = 0.f;
        #pragma unroll
        for (int j=0;j<4;j++) acc[i][j]=0.f;
    }
    __syncthreads();
    for (int kt=0; kt<=qt; kt++){
        int k0 = kt*64;
        #pragma unroll
        for (int rep=0;rep<4;rep++){
            int lin = tid + rep*256;
            int r = lin >> 4, c = (lin & 15)*4;
            float4 kv = *(const float4*)(Kg + base + (size_t)(k0+r)*Dn + c);
            KVs[(c+0)*64 + r] = kv.x;
            KVs[(c+1)*64 + r] = kv.y;
            KVs[(c+2)*64 + r] = kv.z;
            KVs[(c+3)*64 + r] = kv.w;
        }
        __syncthreads();
        float s[4][4];
        #pragma unroll
        for (int i=0;i<4;i++)
            #pragma unroll
            for (int j=0;j<4;j++) s[i][j]=0.f;
        #pragma unroll 4
        for (int d=0; d<64; d++){
            float qa[4], kb[4];
            #pragma unroll
            for (int i=0;i<4;i++) qa[i] = Qs[(ty*4+i)*64 + d];
            #pragma unroll
            for (int j=0;j<4;j++) kb[j] = KVs[d*64 + tx*4 + j];
            #pragma unroll
            for (int i=0;i<4;i++)
                #pragma unroll
                for (int j=0;j<4;j++) s[i][j] = fmaf(qa[i], kb[j], s[i][j]);
        }
        #pragma unroll
        for (int i=0;i<4;i++){
            int qq = q0 + ty*4 + i;
            #pragma unroll
            for (int j=0;j<4;j++){
                int kk = k0 + tx*4 + j;
                s[i][j] = (kk <= qq) ? s[i][j]*0.125f : -1e30f;
            }
        }
        #pragma unroll
        for (int i=0;i<4;i++){
            float mt = fmaxf(fmaxf(s[i][0],s[i][1]), fmaxf(s[i][2],s[i][3]));
            #pragma unroll
            for (int o=8;o;o>>=1) mt = fmaxf(mt, __shfl_xor_sync(0xffffffffu, mt, o));
            float mn = fmaxf(mrow[i], mt);
            float corr = __expf(mrow[i] - mn);
            float rs = 0.f;
            #pragma unroll
            for (int j=0;j<4;j++){ float p = __expf(s[i][j]-mn); s[i][j]=p; rs+=p; }
            #pragma unroll
            for (int o=8;o;o>>=1) rs += __shfl_xor_sync(0xffffffffu, rs, o);
            lrow[i] = lrow[i]*corr + rs;
            mrow[i] = mn;
            #pragma unroll
            for (int j=0;j<4;j++) acc[i][j] *= corr;
            #pragma unroll
            for (int j=0;j<4;j++) Ps[(ty*4+i)*64 + tx*4+j] = s[i][j];
        }
        __syncthreads();
        #pragma unroll
        for (int rep=0;rep<4;rep++){
            int lin = tid + rep*256;
            int r = lin >> 4, c = (lin & 15)*4;
            *(float4*)&KVs[r*64+c] = *(const float4*)(V + base + (size_t)(k0+r)*Dn + c);
        }
        __syncthreads();
        #pragma unroll 4
        for (int kv=0; kv<64; kv++){
            float pv[4], vv[4];
            #pragma unroll
            for (int i=0;i<4;i++) pv[i] = Ps[(ty*4+i)*64 + kv];
            #pragma unroll
            for (int j=0;j<4;j++) vv[j] = KVs[kv*64 + tx*4 + j];
            #pragma unroll
            for (int i=0;i<4;i++)
                #pragma unroll
                for (int j=0;j<4;j++) acc[i][j] = fmaf(pv[i], vv[j], acc[i][j]);
        }
        __syncthreads();
    }
    #pragma unroll
    for (int i=0;i<4;i++){
        float inv = 1.f/lrow[i];
        size_t o = base + (size_t)(q0+ty*4+i)*Dn + tx*4;
        __half2 p0 = __floats2half2_rn(acc[i][0]*inv, acc[i][1]*inv);
        __half2 p1 = __floats2half2_rn(acc[i][2]*inv, acc[i][3]*inv);
        *(__half2*)(O + o)     = p0;
        *(__half2*)(O + o + 2) = p1;
    }
}

// =============================== gating / MoE ================================
__global__ void k_gate(const float* __restrict__ xn, const float* __restrict__ gw)
{
    int t = blockIdx.x;
    int w = threadIdx.x >> 5, lane = threadIdx.x & 31;
    const float* xr = xn + (size_t)t * Dn;
    const float* gr = gw + (size_t)w * Dn;
    float acc = 0.f;
    for (int d = lane; d < Dn; d += 32) acc = fmaf(xr[d], gr[d], acc);
    #pragma unroll
    for (int o=16;o;o>>=1) acc += __shfl_xor_sync(0xffffffffu, acc, o);
    __shared__ float lg[En];
    if (lane == 0) lg[w] = acc;
    __syncthreads();
    if (threadIdx.x == 0){
        int i1 = 0;
        for (int e=1;e<En;e++) if (lg[e] > lg[i1]) i1 = e;
        int i2 = -1;
        for (int e=0;e<En;e++){
            if (e == i1) continue;
            if (i2 < 0 || lg[e] > lg[i2]) i2 = e;
        }
        float l1 = lg[i1], l2 = lg[i2];
        float e2 = expf(l2 - l1);
        float inv = 1.f/(1.f + e2);
        float gv1 = inv, gv2 = e2*inv;
        g_expid[t*2]   = i1; g_expid[t*2+1]   = i2;
        g_gateval[t*2] = gv1; g_gateval[t*2+1] = gv2;
        atomicAdd(&g_cnt[i1], 1); atomicAdd(&g_cnt[i2], 1);
        atomicAdd(&g_gsum[i1], gv1); atomicAdd(&g_gsum[i2], gv2);
        float mx = lg[0];
        for (int e=1;e<En;e++) mx = fmaxf(mx, lg[e]);
        float pe[En]; float se = 0.f;
        for (int e=0;e<En;e++){ pe[e] = expf(lg[e]-mx); se += pe[e]; }
        float pinv = 1.f/se;
        for (int e=0;e<En;e++) atomicAdd(&g_psum[e], pe[e]*pinv);
    }
}

__global__ void k_offsets(float* __restrict__ out, int write_aux)
{
    __shared__ int soff[En+1];
    if (threadIdx.x == 0){
        int tot = 0;
        for (int e=0;e<En;e++){
            soff[e] = tot;
            g_cursor[e] = tot;
            tot += ((g_cnt[e] + 127) >> 7) << 7;
        }
        soff[En] = tot;
        g_totalrows = tot;
        if (write_aux){
            float sacc = 0.f;
            for (int e=0;e<En;e++) sacc += g_gsum[e]*g_psum[e];
            out[(size_t)Tn*Dn] = (float)En * sacc / ((float)Tn*(float)Tn);
        }
    }
    __syncthreads();
    int tot = soff[En];
    for (int r = threadIdx.x; r < tot; r += blockDim.x){
        int e = 0;
        while (e+1 < En && r >= soff[e+1]) e++;
        g_rowexp[r] = e;
        g_rowtok[r] = -1;
    }
}

__global__ void k_scatter()
{
    int t = blockIdx.x*blockDim.x + threadIdx.x;
    if (t >= Tn) return;
    #pragma unroll
    for (int k=0;k<2;k++){
        int e = g_expid[t*2+k];
        int pos = atomicAdd(&g_cursor[e], 1);
        g_rowtok[pos] = t;
        g_rowgate[pos] = g_gateval[t*2+k];
    }
}

// H = silu(G) * U  -> fp16 Hh
__global__ void k_silumul()
{
    size_t i4 = ((size_t)blockIdx.x*blockDim.x + threadIdx.x) * 4;
    size_t n = (size_t)g_totalrows * HIDn;
    if (i4 >= n) return;
    float4 g = *(float4*)&g_GBUF[i4];
    float4 u = *(float4*)&g_UBUF[i4];
    float a = (g.x / (1.f + __expf(-g.x))) * u.x;
    float b = (g.y / (1.f + __expf(-g.y))) * u.y;
    float c = (g.z / (1.f + __expf(-g.z))) * u.z;
    float d = (g.w / (1.f + __expf(-g.w))) * u.w;
    __half2 h0 = __floats2half2_rn(a, b);
    __half2 h1 = __floats2half2_rn(c, d);
    uint2 o;
    o.x = *reinterpret_cast<uint32_t*>(&h0);
    o.y = *reinterpret_cast<uint32_t*>(&h1);
    *(uint2*)&g_Hh[i4] = o;
}

// ---------------------------------------------------------------------------
extern "C" void kernel_launch(void* const* d_in, const int* in_sizes, int n_in,
                              void* d_out, int out_size)
{
    (void)in_sizes; (void)n_in;
    const float* x   = (const float*)d_in[0];
    const float* wq  = (const float*)d_in[1];
    const float* wk  = (const float*)d_in[2];
    const float* wv  = (const float*)d_in[3];
    const float* wo  = (const float*)d_in[4];
    const float* anw = (const float*)d_in[5];
    const float* fnw = (const float*)d_in[6];
    const float* gw  = (const float*)d_in[7];
    const float* wge = (const float*)d_in[8];
    const float* wue = (const float*)d_in[9];
    const float* wde = (const float*)d_in[10];
    float* out = (float*)d_out;

    float *pQ,*pK,*pV,*pH,*pXN2,*pG,*pU;
    __half *pXNh,*pATTh,*pXN2h,*pHh,*pWqh,*pWkh,*pWvh,*pWoh,*pWgeh,*pWueh,*pWdeh;
    cudaGetSymbolAddress((void**)&pQ,    g_Qb);
    cudaGetSymbolAddress((void**)&pK,    g_Kb);
    cudaGetSymbolAddress((void**)&pV,    g_Vb);
    cudaGetSymbolAddress((void**)&pH,    g_Hb);
    cudaGetSymbolAddress((void**)&pXN2,  g_XN2);
    cudaGetSymbolAddress((void**)&pG,    g_GBUF);
    cudaGetSymbolAddress((void**)&pU,    g_UBUF);
    cudaGetSymbolAddress((void**)&pXNh,  g_XNh);
    cudaGetSymbolAddress((void**)&pATTh, g_ATTh);
    cudaGetSymbolAddress((void**)&pXN2h, g_XN2h);
    cudaGetSymbolAddress((void**)&pHh,   g_Hh);
    cudaGetSymbolAddress((void**)&pWqh,  g_Wqh);
    cudaGetSymbolAddress((void**)&pWkh,  g_Wkh);
    cudaGetSymbolAddress((void**)&pWvh,  g_Wvh);
    cudaGetSymbolAddress((void**)&pWoh,  g_Woh);
    cudaGetSymbolAddress((void**)&pWgeh, g_Wgeh);
    cudaGetSymbolAddress((void**)&pWueh, g_Wueh);
    cudaGetSymbolAddress((void**)&pWdeh, g_Wdeh);

    cudaFuncSetAttribute(k_gemm<16,EPI_PLAIN,false,false>,
                         cudaFuncAttributeMaxDynamicSharedMemorySize, GEMM_SMEM);
    cudaFuncSetAttribute(k_gemm<16,EPI_RESID,false,false>,
                         cudaFuncAttributeMaxDynamicSharedMemorySize, GEMM_SMEM);
    cudaFuncSetAttribute(k_gemm<16,EPI_PLAIN,true,true>,
                         cudaFuncAttributeMaxDynamicSharedMemorySize, GEMM_SMEM);
    cudaFuncSetAttribute(k_gemm<64,EPI_DOWN,false,true>,
                         cudaFuncAttributeMaxDynamicSharedMemorySize, GEMM_SMEM);

    k_reset<<<1, 32>>>();

    // weight conversion fp32 -> fp16
    {
        int n4 = Dn*Dn/4, blk = 256, g1 = (n4+blk-1)/blk;
        k_f2h<<<g1, blk>>>((const float4*)wq, (uint2*)pWqh, n4);
        k_f2h<<<g1, blk>>>((const float4*)wk, (uint2*)pWkh, n4);
        k_f2h<<<g1, blk>>>((const float4*)wv, (uint2*)pWvh, n4);
        k_f2h<<<g1, blk>>>((const float4*)wo, (uint2*)pWoh, n4);
        int ne4 = En*HIDn*(Dn/4), g2 = (ne4+blk-1)/blk;
        k_f2h<<<g2, blk>>>((const float4*)wge, (uint2*)pWgeh, ne4);
        k_f2h<<<g2, blk>>>((const float4*)wue, (uint2*)pWueh, ne4);
        k_f2h<<<g2, blk>>>((const float4*)wde, (uint2*)pWdeh, ne4);
    }

    // attn pre-norm (fp16 only)
    k_rmsnorm<<<Tn, 256>>>(x, anw, nullptr, pXNh);

    // QKV projections (one launch, z selects weight/output)
    k_gemm<16,EPI_PLAIN,false,false><<<dim3(8,16,3), 256, GEMM_SMEM>>>(
        pXNh, Dn, pWqh, pWkh, pWvh, 0, Dn, pQ, pK, pV, Dn, nullptr, nullptr);

    // RoPE
    int nrope = Tn*NHn*32;
    k_rope<<<nrope/256, 256>>>(pQ);
    k_rope<<<nrope/256, 256>>>(pK);

    // attention (fp32 compute, fp16 output)
    k_attn<<<dim3(Bn*NHn, Sn/64), 256>>>(pQ, pK, pV, pATTh);

    // out proj + residual (writes H and d_out)
    k_gemm<16,EPI_RESID,false,false><<<dim3(8,16,1), 256, GEMM_SMEM>>>(
        pATTh, Dn, pWoh, pWoh, pWoh, 0, Dn, pH, pH, pH, Dn, x, out);

    // ffn pre-norm (fp32 for gating + fp16 for GEMMs)
    k_rmsnorm<<<Tn, 256>>>(pH, fnw, pXN2, pXN2h);

    // gating + routing
    k_gate<<<Tn, 256>>>(pXN2, gw);
    int write_aux = (out_size > Tn*Dn) ? 1 : 0;
    k_offsets<<<1, 256>>>(out, write_aux);
    k_scatter<<<(Tn+255)/256, 256>>>();

    // expert gate/up GEMMs (gathered rows; z selects gate vs up)
    k_gemm<16,EPI_PLAIN,true,true><<<dim3(32, MAXROWS/128, 2), 256, GEMM_SMEM>>>(
        pXN2h, Dn, pWgeh, pWueh, pWueh, (long)HIDn*Dn, Dn, pG, pU, pU, HIDn,
        nullptr, nullptr);

    // SwiGLU elementwise -> fp16
    k_silumul<<<(MAXROWS*(HIDn/4))/256, 256>>>();

    // down GEMM + gated scatter-add into out
    k_gemm<64,EPI_DOWN,false,true><<<dim3(8, MAXROWS/128, 1), 256, GEMM_SMEM>>>(
        pHh, HIDn, pWdeh, pWdeh, pWdeh, (long)Dn*HIDn, HIDn, out, out, out, Dn,
        nullptr, nullptr);
}